// round 16
// baseline (speedup 1.0000x reference)
#include <cuda_runtime.h>
#include <cuda_fp16.h>
#include <cuda_bf16.h>
#include <mma.h>
using namespace nvcuda;

#define N_NODES 100000
#define N_EDGES 3200000
#define HID 64
#define CAP 128   // bucket capacity per dst (deg ~ Poisson(32); P(>128) ~ 0)
#define DN 128    // nodes per dense block (dynamic smem)

// ---------------- scratch (static device globals; zero-init, self-cleaning) ----------
__device__ int          g_cnt[N_NODES];              // degree/cursor; zeroed by k_out
__device__ int2         g_edge[N_NODES * CAP];       // {src, bitcast(w)} per-dst buckets
__device__ float        g_a1[N_NODES];               // REDG by scatter; zeroed by k_dense
__device__ unsigned int g_g1h[N_NODES * (HID / 2)];  // h1@W2_rel as half2
__device__ unsigned int g_p2h[N_NODES * (HID / 2)];  // b2 + h1@W2_root as half2
__device__ float        g_s[N_NODES];                // h2 . W3_rel
__device__ float        g_t[N_NODES];                // h2 . W3_root

// ---- cheap per-block dtype probe: 128 odd 32-bit words (512 B, L1-resident) --------
__device__ __forceinline__ int block_detect_is64(const unsigned int* w, int tid,
                                                 int* s_flag) {
    if (tid < 32) {
        unsigned int v = 0;
        #pragma unroll
        for (int k = 0; k < 4; k++) v |= w[2 * (tid + 32 * k) + 1];
        #pragma unroll
        for (int off = 16; off > 0; off >>= 1)
            v |= __shfl_down_sync(0xFFFFFFFFu, v, off);
        if (tid == 0) *s_flag = (v == 0) ? 1 : 0;
    }
    __syncthreads();
    return *s_flag;
}

// ---------------- K1: scatter into fixed-cap buckets + fused layer-1 agg (REDG) ------
__global__ void k_scatter(const void* __restrict__ ei_raw,
                          const float* __restrict__ ew,
                          const float* __restrict__ x) {
    __shared__ int s_is64;
    int tid = threadIdx.x;
    int is64 = block_detect_is64((const unsigned int*)ei_raw, tid, &s_is64);
    long long e0 = (long long)(blockIdx.x * blockDim.x + tid) * 8;
    if (e0 >= N_EDGES) return;
    int s[8], d[8];
    if (is64) {
        const long long* ei = (const long long*)ei_raw;
        #pragma unroll
        for (int k = 0; k < 4; k++) {
            longlong2 sp = ((const longlong2*)ei)[e0 / 2 + k];
            longlong2 dp = ((const longlong2*)(ei + N_EDGES))[e0 / 2 + k];
            s[2 * k] = (int)sp.x; s[2 * k + 1] = (int)sp.y;
            d[2 * k] = (int)dp.x; d[2 * k + 1] = (int)dp.y;
        }
    } else {
        const int* ei = (const int*)ei_raw;
        #pragma unroll
        for (int k = 0; k < 2; k++) {
            int4 sp = ((const int4*)ei)[e0 / 4 + k];
            int4 dp = ((const int4*)(ei + N_EDGES))[e0 / 4 + k];
            s[4 * k] = sp.x; s[4 * k + 1] = sp.y; s[4 * k + 2] = sp.z; s[4 * k + 3] = sp.w;
            d[4 * k] = dp.x; d[4 * k + 1] = dp.y; d[4 * k + 2] = dp.z; d[4 * k + 3] = dp.w;
        }
    }
    float w[8];
    #pragma unroll
    for (int k = 0; k < 2; k++) {
        float4 w4 = ((const float4*)ew)[e0 / 4 + k];
        w[4 * k] = w4.x; w[4 * k + 1] = w4.y; w[4 * k + 2] = w4.z; w[4 * k + 3] = w4.w;
    }
    float xv[8];
    #pragma unroll
    for (int k = 0; k < 8; k++) xv[k] = __ldg(&x[s[k]]);
    int slot[8];
    #pragma unroll
    for (int k = 0; k < 8; k++) slot[k] = atomicAdd(&g_cnt[d[k]], 1);
    #pragma unroll
    for (int k = 0; k < 8; k++)
        if (slot[k] < CAP)
            g_edge[d[k] * CAP + slot[k]] = make_int2(s[k], __float_as_int(w[k]));
    #pragma unroll
    for (int k = 0; k < 8; k++) atomicAdd(&g_a1[d[k]], w[k] * xv[k]);   // REDG (no return)
}

// ---------------- K2: dense via tensor cores, DN=128, dynamic smem, PDL --------------
__global__ void __launch_bounds__(256) k_dense(
    const float* __restrict__ x,
    const float* __restrict__ W1_rel, const float* __restrict__ b1,
    const float* __restrict__ W1_root,
    const float* __restrict__ W2_rel, const float* __restrict__ b2,
    const float* __restrict__ W2_root)
{
    extern __shared__ char smem[];
    float*  sC   = (float*)smem;                                   // DN*HID fp32
    __half* sA   = (__half*)(smem + DN * HID * 4);                 // DN*72 half
    __half* sBr  = (__half*)(smem + DN * HID * 4 + DN * 72 * 2);   // HID*HID half
    __half* sBo  = sBr + HID * HID;
    float*  sW1r = (float*)(sBo + HID * HID);
    float*  sW1o = sW1r + HID;
    float*  sB1  = sW1o + HID;
    float*  sB2  = sB1 + HID;

    int tid = threadIdx.x;
    int warp = tid >> 5;                 // 8 warps, one 16-row band each
    int i0 = blockIdx.x * DN;

    // ---- prologue: weight staging overlaps scatter tail (PDL)
    if (tid < HID) {
        sW1r[tid] = W1_rel[tid];
        sW1o[tid] = W1_root[tid];
        sB1[tid]  = b1[tid];
        sB2[tid]  = b2[tid];
    }
    for (int k = tid; k < HID * HID / 2; k += 256) {
        float2 r = ((const float2*)W2_rel)[k];
        float2 o = ((const float2*)W2_root)[k];
        ((__half2*)sBr)[k] = __floats2half2_rn(r.x, r.y);
        ((__half2*)sBo)[k] = __floats2half2_rn(o.x, o.y);
    }
    cudaGridDependencySynchronize();     // wait for scatter before touching g_a1
    __syncthreads();

    {
        int n  = tid >> 1;
        int c0 = (tid & 1) * 32;
        int gi = i0 + n;
        float ai = 0.f, xi = 0.f;
        if (gi < N_NODES) {
            ai = g_a1[gi];
            xi = x[gi];
            if ((tid & 1) == 0) g_a1[gi] = 0.f;   // self-clean for next call
        }
        for (int c = c0; c < c0 + 32; c += 2) {
            float h0 = fmaxf(fmaf(ai, sW1r[c],     fmaf(xi, sW1o[c],     sB1[c])),     0.f);
            float h1 = fmaxf(fmaf(ai, sW1r[c + 1], fmaf(xi, sW1o[c + 1], sB1[c + 1])), 0.f);
            *(__half2*)&sA[n * 72 + c] = __floats2half2_rn(h0, h1);
        }
    }
    __syncthreads();

    #pragma unroll
    for (int m = 0; m < 2; m++) {
        const __half* B = (m == 0) ? sBr : sBo;
        #pragma unroll
        for (int nt = 0; nt < 4; nt++) {
            wmma::fragment<wmma::accumulator, 16, 16, 16, float> c_frag;
            wmma::fill_fragment(c_frag, 0.f);
            #pragma unroll
            for (int kt = 0; kt < 4; kt++) {
                wmma::fragment<wmma::matrix_a, 16, 16, 16, __half, wmma::row_major> a_frag;
                wmma::fragment<wmma::matrix_b, 16, 16, 16, __half, wmma::row_major> b_frag;
                wmma::load_matrix_sync(a_frag, &sA[(warp * 16) * 72 + kt * 16], 72);
                wmma::load_matrix_sync(b_frag, B + (kt * 16) * HID + nt * 16, HID);
                wmma::mma_sync(c_frag, a_frag, b_frag, c_frag);
            }
            wmma::store_matrix_sync(&sC[(warp * 16) * HID + nt * 16], c_frag, HID,
                                    wmma::mem_row_major);
        }
        __syncthreads();
        if (m == 0) {
            for (int idx = tid; idx < DN * 32; idx += 256) {
                int n = idx >> 5, cp = idx & 31;
                int gi = i0 + n;
                if (gi < N_NODES) {
                    __half2 p = __floats2half2_rn(sC[n * HID + 2 * cp],
                                                  sC[n * HID + 2 * cp + 1]);
                    g_g1h[gi * 32 + cp] = *(unsigned int*)&p;
                }
            }
        } else {
            for (int idx = tid; idx < DN * 32; idx += 256) {
                int n = idx >> 5, cp = idx & 31;
                int gi = i0 + n;
                if (gi < N_NODES) {
                    __half2 p = __floats2half2_rn(sC[n * HID + 2 * cp]     + sB2[2 * cp],
                                                  sC[n * HID + 2 * cp + 1] + sB2[2 * cp + 1]);
                    g_p2h[gi * 32 + cp] = *(unsigned int*)&p;
                }
            }
        }
        __syncthreads();
    }
}

static const int DENSE_SMEM = DN * HID * 4 + DN * 72 * 2 + 2 * HID * HID * 2 + 4 * HID * 4;

// ---------------- K3: layer-2 aggregation, 2 warps per node, LDG.128 geometry --------
// Each warp pair splits a node's edge list in half. Per warp: 8 lanes per edge
// (uint4 = 8 fp16 cols/lane), 4 edges per group. Partials merge via smem.
__global__ void __launch_bounds__(256) k_agg2(
    const float* __restrict__ W3_rel, const float* __restrict__ W3_root)
{
    __shared__ float sW3r[HID], sW3o[HID];
    __shared__ float sPart[4][8][8];     // [pair][q][8 cols]
    int tid = threadIdx.x;
    if (tid < HID) { sW3r[tid] = W3_rel[tid]; sW3o[tid] = W3_root[tid]; }
    cudaGridDependencySynchronize();     // wait for dense before touching g_g1h/g_p2h
    __syncthreads();

    int warp = tid >> 5;                 // 0..7
    int pair = warp >> 1;                // 0..3
    int wb   = warp & 1;                 // 0 = A (low half), 1 = B (high half)
    int lane = tid & 31;
    int i = blockIdx.x * 4 + pair;       // grid is exact: 100000/4 = 25000 blocks
    int deg = g_cnt[i]; if (deg > CAP) deg = CAP;
    int halfdeg = (deg + 1) >> 1;
    int ebeg = wb ? halfdeg : 0;
    int eend = wb ? deg : halfdeg;

    const uint4* g1h4 = (const uint4*)g_g1h;   // 8 uint4 per node row
    int sub = lane >> 3;    // which edge of the group of 4
    int q   = lane & 7;     // col group: cols 8q..8q+7

    float4 accA = make_float4(0.f, 0.f, 0.f, 0.f);
    float4 accB = make_float4(0.f, 0.f, 0.f, 0.f);

    for (int base = ebeg; base < eend; base += 32) {
        int n = eend - base; if (n > 32) n = 32;
        int2 ed = (lane < n) ? g_edge[i * CAP + base + lane] : make_int2(0, 0);
        int groups = (n + 3) >> 2;
        #pragma unroll 4
        for (int g = 0; g < groups; g++) {
            int   el = g * 4 + sub;
            int   sv = __shfl_sync(0xFFFFFFFFu, ed.x, el);
            float w  = __int_as_float(__shfl_sync(0xFFFFFFFFu, ed.y, el));
            uint4 p  = __ldg(&g1h4[sv * 8 + q]);
            float2 f0 = __half22float2(*(__half2*)&p.x);
            float2 f1 = __half22float2(*(__half2*)&p.y);
            float2 f2 = __half22float2(*(__half2*)&p.z);
            float2 f3 = __half22float2(*(__half2*)&p.w);
            accA.x = fmaf(w, f0.x, accA.x);
            accA.y = fmaf(w, f0.y, accA.y);
            accA.z = fmaf(w, f1.x, accA.z);
            accA.w = fmaf(w, f1.y, accA.w);
            accB.x = fmaf(w, f2.x, accB.x);
            accB.y = fmaf(w, f2.y, accB.y);
            accB.z = fmaf(w, f3.x, accB.z);
            accB.w = fmaf(w, f3.y, accB.w);
        }
    }
    // merge the 4 edge sub-groups within the warp
    #pragma unroll
    for (int off = 8; off <= 16; off <<= 1) {
        accA.x += __shfl_xor_sync(0xFFFFFFFFu, accA.x, off);
        accA.y += __shfl_xor_sync(0xFFFFFFFFu, accA.y, off);
        accA.z += __shfl_xor_sync(0xFFFFFFFFu, accA.z, off);
        accA.w += __shfl_xor_sync(0xFFFFFFFFu, accA.w, off);
        accB.x += __shfl_xor_sync(0xFFFFFFFFu, accB.x, off);
        accB.y += __shfl_xor_sync(0xFFFFFFFFu, accB.y, off);
        accB.z += __shfl_xor_sync(0xFFFFFFFFu, accB.z, off);
        accB.w += __shfl_xor_sync(0xFFFFFFFFu, accB.w, off);
    }
    // warp B publishes its partials
    if (wb == 1 && lane < 8) {
        sPart[pair][lane][0] = accA.x; sPart[pair][lane][1] = accA.y;
        sPart[pair][lane][2] = accA.z; sPart[pair][lane][3] = accA.w;
        sPart[pair][lane][4] = accB.x; sPart[pair][lane][5] = accB.y;
        sPart[pair][lane][6] = accB.z; sPart[pair][lane][7] = accB.w;
    }
    __syncthreads();
    if (wb == 1) return;                 // warp A finishes the node

    accA.x += sPart[pair][q][0]; accA.y += sPart[pair][q][1];
    accA.z += sPart[pair][q][2]; accA.w += sPart[pair][q][3];
    accB.x += sPart[pair][q][4]; accB.y += sPart[pair][q][5];
    accB.z += sPart[pair][q][6]; accB.w += sPart[pair][q][7];

    // p2 (fp16) add, relu, fold layer-3 projections (cols 8q..8q+7)
    uint4 pp = __ldg(&((const uint4*)g_p2h)[i * 8 + q]);
    float2 q0 = __half22float2(*(__half2*)&pp.x);
    float2 q1 = __half22float2(*(__half2*)&pp.y);
    float2 q2 = __half22float2(*(__half2*)&pp.z);
    float2 q3 = __half22float2(*(__half2*)&pp.w);
    float h0 = fmaxf(accA.x + q0.x, 0.f);
    float h1 = fmaxf(accA.y + q0.y, 0.f);
    float h2 = fmaxf(accA.z + q1.x, 0.f);
    float h3 = fmaxf(accA.w + q1.y, 0.f);
    float h4 = fmaxf(accB.x + q2.x, 0.f);
    float h5 = fmaxf(accB.y + q2.y, 0.f);
    float h6 = fmaxf(accB.z + q3.x, 0.f);
    float h7 = fmaxf(accB.w + q3.y, 0.f);

    int c0 = 8 * q;
    float sp = h0 * sW3r[c0]     + h1 * sW3r[c0 + 1] + h2 * sW3r[c0 + 2]
             + h3 * sW3r[c0 + 3] + h4 * sW3r[c0 + 4] + h5 * sW3r[c0 + 5]
             + h6 * sW3r[c0 + 6] + h7 * sW3r[c0 + 7];
    float tp = h0 * sW3o[c0]     + h1 * sW3o[c0 + 1] + h2 * sW3o[c0 + 2]
             + h3 * sW3o[c0 + 3] + h4 * sW3o[c0 + 4] + h5 * sW3o[c0 + 5]
             + h6 * sW3o[c0 + 6] + h7 * sW3o[c0 + 7];
    #pragma unroll
    for (int off = 4; off > 0; off >>= 1) {
        sp += __shfl_xor_sync(0xFFFFFFFFu, sp, off);
        tp += __shfl_xor_sync(0xFFFFFFFFu, tp, off);
    }
    if (lane == 0) { g_s[i] = sp; g_t[i] = tp; }
}

// ---------------- K4: layer-3 scalar aggregation, 2 nodes per warp, PDL --------------
__global__ void __launch_bounds__(256) k_out(const float* __restrict__ b3,
                                             float* __restrict__ out) {
    cudaGridDependencySynchronize();     // wait for agg2 before touching g_s/g_t
    int wid_g = (blockIdx.x * 256 + threadIdx.x) >> 5;
    int lane = threadIdx.x & 31;
    int half = lane >> 4;
    int l = lane & 15;
    int i = wid_g * 2 + half;
    if (i >= N_NODES) return;
    int deg = g_cnt[i]; if (deg > CAP) deg = CAP;
    const int4* eb = (const int4*)(g_edge + i * CAP);
    int pairs = deg >> 1;
    float acc = 0.f;
    for (int p = l; p < pairs; p += 16) {
        int4 e2 = __ldg(&eb[p]);
        acc = fmaf(__int_as_float(e2.y), __ldg(&g_s[e2.x]), acc);
        acc = fmaf(__int_as_float(e2.w), __ldg(&g_s[e2.z]), acc);
    }
    if ((deg & 1) && l == 0) {
        int2 ed = g_edge[i * CAP + deg - 1];
        acc = fmaf(__int_as_float(ed.y), g_s[ed.x], acc);
    }
    #pragma unroll
    for (int off = 1; off <= 8; off <<= 1)
        acc += __shfl_xor_sync(0xFFFFFFFFu, acc, off);
    if (l == 0) {
        g_cnt[i] = 0;                          // self-clean for next call
        out[i] = acc + b3[0] + g_t[i];
    }
}

// ---------------- launch (PDL on the dependent chain) ----------------
static void launch_pdl(const void* fn, dim3 grid, dim3 block, size_t smem,
                       void** args) {
    cudaLaunchConfig_t cfg = {};
    cfg.gridDim = grid;
    cfg.blockDim = block;
    cfg.dynamicSmemBytes = smem;
    cfg.stream = 0;
    cudaLaunchAttribute attr[1];
    attr[0].id = cudaLaunchAttributeProgrammaticStreamSerialization;
    attr[0].val.programmaticStreamSerializationAllowed = 1;
    cfg.attrs = attr;
    cfg.numAttrs = 1;
    cudaLaunchKernelExC(&cfg, fn, args);
}

extern "C" void kernel_launch(void* const* d_in, const int* in_sizes, int n_in,
                              void* d_out, int out_size) {
    const float* x       = (const float*)d_in[0];
    const void*  ei_raw  = d_in[1];
    const float* ew      = (const float*)d_in[2];
    const float* W1_rel  = (const float*)d_in[3];
    const float* b1      = (const float*)d_in[4];
    const float* W1_root = (const float*)d_in[5];
    const float* W2_rel  = (const float*)d_in[6];
    const float* b2      = (const float*)d_in[7];
    const float* W2_root = (const float*)d_in[8];
    const float* W3_rel  = (const float*)d_in[9];
    const float* b3      = (const float*)d_in[10];
    const float* W3_root = (const float*)d_in[11];
    float* out = (float*)d_out;

    cudaFuncSetAttribute(k_dense, cudaFuncAttributeMaxDynamicSharedMemorySize,
                         DENSE_SMEM);

    k_scatter<<<(N_EDGES / 8 + 255) / 256, 256>>>(ei_raw, ew, x);

    {
        void* args[] = {(void*)&x, (void*)&W1_rel, (void*)&b1, (void*)&W1_root,
                        (void*)&W2_rel, (void*)&b2, (void*)&W2_root};
        launch_pdl((const void*)k_dense, dim3((N_NODES + DN - 1) / DN), dim3(256),
                   DENSE_SMEM, args);
    }
    {
        void* args[] = {(void*)&W3_rel, (void*)&W3_root};
        launch_pdl((const void*)k_agg2, dim3(N_NODES / 4), dim3(256), 0, args);
    }
    {
        void* args[] = {(void*)&b3, (void*)&out};
        launch_pdl((const void*)k_out, dim3(((N_NODES + 1) / 2 * 32 + 255) / 256),
                   dim3(256), 0, args);
    }
}

// round 17
// speedup vs baseline: 1.1070x; 1.1070x over previous
#include <cuda_runtime.h>
#include <cuda_fp16.h>
#include <cuda_bf16.h>
#include <mma.h>
using namespace nvcuda;

#define N_NODES 100000
#define N_EDGES 3200000
#define HID 64
#define CAP 128   // bucket capacity per dst (deg ~ Poisson(32); P(>128) ~ 0)
#define DN 128    // nodes per dense block (dynamic smem)

// ---------------- scratch (static device globals; zero-init, self-cleaning) ----------
__device__ int          g_cnt[N_NODES];              // degree/cursor; zeroed by k_out
__device__ int2         g_edge[N_NODES * CAP];       // {src, bitcast(w)} per-dst buckets
__device__ float        g_a1[N_NODES];               // REDG by scatter; zeroed by k_dense
__device__ unsigned int g_g1h[N_NODES * (HID / 2)];  // h1@W2_rel as half2
__device__ float4       g_p2[N_NODES * HID / 4];     // b2 + h1@W2_root (fp32)
__device__ float        g_s[N_NODES];                // h2 . W3_rel
__device__ float        g_t[N_NODES];                // h2 . W3_root

// ---- cheap per-block dtype probe: 128 odd 32-bit words (512 B, L1-resident) --------
__device__ __forceinline__ int block_detect_is64(const unsigned int* w, int tid,
                                                 int* s_flag) {
    if (tid < 32) {
        unsigned int v = 0;
        #pragma unroll
        for (int k = 0; k < 4; k++) v |= w[2 * (tid + 32 * k) + 1];
        #pragma unroll
        for (int off = 16; off > 0; off >>= 1)
            v |= __shfl_down_sync(0xFFFFFFFFu, v, off);
        if (tid == 0) *s_flag = (v == 0) ? 1 : 0;
    }
    __syncthreads();
    return *s_flag;
}

// ---------------- K1: scatter into fixed-cap buckets + fused layer-1 agg (REDG) ------
__global__ void k_scatter(const void* __restrict__ ei_raw,
                          const float* __restrict__ ew,
                          const float* __restrict__ x) {
    __shared__ int s_is64;
    int tid = threadIdx.x;
    int is64 = block_detect_is64((const unsigned int*)ei_raw, tid, &s_is64);
    long long e0 = (long long)(blockIdx.x * blockDim.x + tid) * 8;
    if (e0 >= N_EDGES) return;
    int s[8], d[8];
    if (is64) {
        const long long* ei = (const long long*)ei_raw;
        #pragma unroll
        for (int k = 0; k < 4; k++) {
            longlong2 sp = ((const longlong2*)ei)[e0 / 2 + k];
            longlong2 dp = ((const longlong2*)(ei + N_EDGES))[e0 / 2 + k];
            s[2 * k] = (int)sp.x; s[2 * k + 1] = (int)sp.y;
            d[2 * k] = (int)dp.x; d[2 * k + 1] = (int)dp.y;
        }
    } else {
        const int* ei = (const int*)ei_raw;
        #pragma unroll
        for (int k = 0; k < 2; k++) {
            int4 sp = ((const int4*)ei)[e0 / 4 + k];
            int4 dp = ((const int4*)(ei + N_EDGES))[e0 / 4 + k];
            s[4 * k] = sp.x; s[4 * k + 1] = sp.y; s[4 * k + 2] = sp.z; s[4 * k + 3] = sp.w;
            d[4 * k] = dp.x; d[4 * k + 1] = dp.y; d[4 * k + 2] = dp.z; d[4 * k + 3] = dp.w;
        }
    }
    float w[8];
    #pragma unroll
    for (int k = 0; k < 2; k++) {
        float4 w4 = ((const float4*)ew)[e0 / 4 + k];
        w[4 * k] = w4.x; w[4 * k + 1] = w4.y; w[4 * k + 2] = w4.z; w[4 * k + 3] = w4.w;
    }
    float xv[8];
    #pragma unroll
    for (int k = 0; k < 8; k++) xv[k] = __ldg(&x[s[k]]);
    int slot[8];
    #pragma unroll
    for (int k = 0; k < 8; k++) slot[k] = atomicAdd(&g_cnt[d[k]], 1);
    #pragma unroll
    for (int k = 0; k < 8; k++)
        if (slot[k] < CAP)
            g_edge[d[k] * CAP + slot[k]] = make_int2(s[k], __float_as_int(w[k]));
    #pragma unroll
    for (int k = 0; k < 8; k++) atomicAdd(&g_a1[d[k]], w[k] * xv[k]);   // REDG (no return)
}

// ---------------- K2: dense via tensor cores, DN=128, dynamic smem, PDL --------------
__global__ void __launch_bounds__(256) k_dense(
    const float* __restrict__ x,
    const float* __restrict__ W1_rel, const float* __restrict__ b1,
    const float* __restrict__ W1_root,
    const float* __restrict__ W2_rel, const float* __restrict__ b2,
    const float* __restrict__ W2_root)
{
    extern __shared__ char smem[];
    float*  sC   = (float*)smem;                                   // DN*HID fp32
    __half* sA   = (__half*)(smem + DN * HID * 4);                 // DN*72 half
    __half* sBr  = (__half*)(smem + DN * HID * 4 + DN * 72 * 2);   // HID*HID half
    __half* sBo  = sBr + HID * HID;
    float*  sW1r = (float*)(sBo + HID * HID);
    float*  sW1o = sW1r + HID;
    float*  sB1  = sW1o + HID;
    float*  sB2  = sB1 + HID;

    int tid = threadIdx.x;
    int warp = tid >> 5;                 // 8 warps, one 16-row band each
    int i0 = blockIdx.x * DN;

    // ---- prologue: weight staging overlaps predecessor tail (PDL)
    if (tid < HID) {
        sW1r[tid] = W1_rel[tid];
        sW1o[tid] = W1_root[tid];
        sB1[tid]  = b1[tid];
        sB2[tid]  = b2[tid];
    }
    for (int k = tid; k < HID * HID / 2; k += 256) {
        float2 r = ((const float2*)W2_rel)[k];
        float2 o = ((const float2*)W2_root)[k];
        ((__half2*)sBr)[k] = __floats2half2_rn(r.x, r.y);
        ((__half2*)sBo)[k] = __floats2half2_rn(o.x, o.y);
    }
    cudaGridDependencySynchronize();     // wait for scatter before touching g_a1
    __syncthreads();

    {
        int n  = tid >> 1;
        int c0 = (tid & 1) * 32;
        int gi = i0 + n;
        float ai = 0.f, xi = 0.f;
        if (gi < N_NODES) {
            ai = g_a1[gi];
            xi = x[gi];
            if ((tid & 1) == 0) g_a1[gi] = 0.f;   // self-clean for next call
        }
        for (int c = c0; c < c0 + 32; c += 2) {
            float h0 = fmaxf(fmaf(ai, sW1r[c],     fmaf(xi, sW1o[c],     sB1[c])),     0.f);
            float h1 = fmaxf(fmaf(ai, sW1r[c + 1], fmaf(xi, sW1o[c + 1], sB1[c + 1])), 0.f);
            *(__half2*)&sA[n * 72 + c] = __floats2half2_rn(h0, h1);
        }
    }
    __syncthreads();

    #pragma unroll
    for (int m = 0; m < 2; m++) {
        const __half* B = (m == 0) ? sBr : sBo;
        #pragma unroll
        for (int nt = 0; nt < 4; nt++) {
            wmma::fragment<wmma::accumulator, 16, 16, 16, float> c_frag;
            wmma::fill_fragment(c_frag, 0.f);
            #pragma unroll
            for (int kt = 0; kt < 4; kt++) {
                wmma::fragment<wmma::matrix_a, 16, 16, 16, __half, wmma::row_major> a_frag;
                wmma::fragment<wmma::matrix_b, 16, 16, 16, __half, wmma::row_major> b_frag;
                wmma::load_matrix_sync(a_frag, &sA[(warp * 16) * 72 + kt * 16], 72);
                wmma::load_matrix_sync(b_frag, B + (kt * 16) * HID + nt * 16, HID);
                wmma::mma_sync(c_frag, a_frag, b_frag, c_frag);
            }
            wmma::store_matrix_sync(&sC[(warp * 16) * HID + nt * 16], c_frag, HID,
                                    wmma::mem_row_major);
        }
        __syncthreads();
        if (m == 0) {
            for (int idx = tid; idx < DN * 32; idx += 256) {
                int n = idx >> 5, cp = idx & 31;
                int gi = i0 + n;
                if (gi < N_NODES) {
                    __half2 p = __floats2half2_rn(sC[n * HID + 2 * cp],
                                                  sC[n * HID + 2 * cp + 1]);
                    g_g1h[gi * 32 + cp] = *(unsigned int*)&p;
                }
            }
        } else {
            for (int idx = tid; idx < DN * 32; idx += 256) {
                int n = idx >> 5, cp = idx & 31;
                int gi = i0 + n;
                if (gi < N_NODES) {
                    float2 f = make_float2(sC[n * HID + 2 * cp]     + sB2[2 * cp],
                                           sC[n * HID + 2 * cp + 1] + sB2[2 * cp + 1]);
                    ((float2*)g_p2)[gi * 32 + cp] = f;
                }
            }
        }
        __syncthreads();
    }
}

static const int DENSE_SMEM = DN * HID * 4 + DN * 72 * 2 + 2 * HID * HID * 2 + 4 * HID * 4;

// ---------------- K3: layer-2 aggregation, LDG.128 + chunk double-buffer, PDL --------
__global__ void __launch_bounds__(256) k_agg2(
    const float* __restrict__ W3_rel, const float* __restrict__ W3_root)
{
    __shared__ float sW3r[HID], sW3o[HID];
    int tid = threadIdx.x;
    if (tid < HID) { sW3r[tid] = W3_rel[tid]; sW3o[tid] = W3_root[tid]; }
    cudaGridDependencySynchronize();     // wait for dense before touching g_g1h/g_p2
    __syncthreads();

    int i = (blockIdx.x * 256 + tid) >> 5;
    int lane = tid & 31;
    if (i >= N_NODES) return;
    int deg = g_cnt[i]; if (deg > CAP) deg = CAP;

    const uint4* g1h4 = (const uint4*)g_g1h;   // 8 uint4 per node row
    int sub = lane >> 3;    // which edge of the group of 4
    int q   = lane & 7;     // col group: cols 8q..8q+7

    float4 accA = make_float4(0.f, 0.f, 0.f, 0.f);
    float4 accB = make_float4(0.f, 0.f, 0.f, 0.f);

    int nch = (deg + 31) >> 5;
    int2 ed_nxt = (deg > 0 && lane < deg) ? g_edge[i * CAP + lane] : make_int2(0, 0);
    for (int c = 0; c < nch; c++) {
        int base = c * 32;
        int n = deg - base; if (n > 32) n = 32;
        int2 ed = ed_nxt;
        if (c + 1 < nch) {               // prefetch next chunk's edges early
            int b2_ = base + 32;
            ed_nxt = (lane < deg - b2_) ? g_edge[i * CAP + b2_ + lane] : make_int2(0, 0);
        }
        int groups = (n + 3) >> 2;
        #pragma unroll 4
        for (int g = 0; g < groups; g++) {
            int   el = g * 4 + sub;
            int   sv = __shfl_sync(0xFFFFFFFFu, ed.x, el);
            float w  = __int_as_float(__shfl_sync(0xFFFFFFFFu, ed.y, el));
            uint4 p  = __ldg(&g1h4[sv * 8 + q]);
            float2 f0 = __half22float2(*(__half2*)&p.x);
            float2 f1 = __half22float2(*(__half2*)&p.y);
            float2 f2 = __half22float2(*(__half2*)&p.z);
            float2 f3 = __half22float2(*(__half2*)&p.w);
            accA.x = fmaf(w, f0.x, accA.x);
            accA.y = fmaf(w, f0.y, accA.y);
            accA.z = fmaf(w, f1.x, accA.z);
            accA.w = fmaf(w, f1.y, accA.w);
            accB.x = fmaf(w, f2.x, accB.x);
            accB.y = fmaf(w, f2.y, accB.y);
            accB.z = fmaf(w, f3.x, accB.z);
            accB.w = fmaf(w, f3.y, accB.w);
        }
    }
    #pragma unroll
    for (int off = 8; off <= 16; off <<= 1) {
        accA.x += __shfl_xor_sync(0xFFFFFFFFu, accA.x, off);
        accA.y += __shfl_xor_sync(0xFFFFFFFFu, accA.y, off);
        accA.z += __shfl_xor_sync(0xFFFFFFFFu, accA.z, off);
        accA.w += __shfl_xor_sync(0xFFFFFFFFu, accA.w, off);
        accB.x += __shfl_xor_sync(0xFFFFFFFFu, accB.x, off);
        accB.y += __shfl_xor_sync(0xFFFFFFFFu, accB.y, off);
        accB.z += __shfl_xor_sync(0xFFFFFFFFu, accB.z, off);
        accB.w += __shfl_xor_sync(0xFFFFFFFFu, accB.w, off);
    }

    float4 p2a = __ldg(&g_p2[i * 16 + 2 * q]);
    float4 p2b = __ldg(&g_p2[i * 16 + 2 * q + 1]);
    float h0 = fmaxf(accA.x + p2a.x, 0.f);
    float h1 = fmaxf(accA.y + p2a.y, 0.f);
    float h2 = fmaxf(accA.z + p2a.z, 0.f);
    float h3 = fmaxf(accA.w + p2a.w, 0.f);
    float h4 = fmaxf(accB.x + p2b.x, 0.f);
    float h5 = fmaxf(accB.y + p2b.y, 0.f);
    float h6 = fmaxf(accB.z + p2b.z, 0.f);
    float h7 = fmaxf(accB.w + p2b.w, 0.f);

    int c0 = 8 * q;
    float sp = h0 * sW3r[c0]     + h1 * sW3r[c0 + 1] + h2 * sW3r[c0 + 2]
             + h3 * sW3r[c0 + 3] + h4 * sW3r[c0 + 4] + h5 * sW3r[c0 + 5]
             + h6 * sW3r[c0 + 6] + h7 * sW3r[c0 + 7];
    float tp = h0 * sW3o[c0]     + h1 * sW3o[c0 + 1] + h2 * sW3o[c0 + 2]
             + h3 * sW3o[c0 + 3] + h4 * sW3o[c0 + 4] + h5 * sW3o[c0 + 5]
             + h6 * sW3o[c0 + 6] + h7 * sW3o[c0 + 7];
    #pragma unroll
    for (int off = 4; off > 0; off >>= 1) {
        sp += __shfl_xor_sync(0xFFFFFFFFu, sp, off);
        tp += __shfl_xor_sync(0xFFFFFFFFu, tp, off);
    }
    if (lane == 0) { g_s[i] = sp; g_t[i] = tp; }
}

// ---------------- K4: layer-3 scalar aggregation, 4 nodes per warp, PDL --------------
__global__ void __launch_bounds__(256) k_out(const float* __restrict__ b3,
                                             float* __restrict__ out) {
    cudaGridDependencySynchronize();     // wait for agg2 before touching g_s/g_t
    int wid_g = (blockIdx.x * 256 + threadIdx.x) >> 5;
    int lane = threadIdx.x & 31;
    int quarter = lane >> 3;             // 0..3
    int l = lane & 7;
    int i = wid_g * 4 + quarter;
    if (i >= N_NODES) return;
    int deg = g_cnt[i]; if (deg > CAP) deg = CAP;
    const int4* eb = (const int4*)(g_edge + i * CAP);
    int pairs = deg >> 1;
    float acc = 0.f;
    for (int p = l; p < pairs; p += 8) {
        int4 e2 = __ldg(&eb[p]);
        acc = fmaf(__int_as_float(e2.y), __ldg(&g_s[e2.x]), acc);
        acc = fmaf(__int_as_float(e2.w), __ldg(&g_s[e2.z]), acc);
    }
    if ((deg & 1) && l == 0) {
        int2 ed = g_edge[i * CAP + deg - 1];
        acc = fmaf(__int_as_float(ed.y), g_s[ed.x], acc);
    }
    #pragma unroll
    for (int off = 1; off <= 4; off <<= 1)      // reduce within each 8-lane quarter
        acc += __shfl_xor_sync(0xFFFFFFFFu, acc, off);
    if (l == 0) {
        g_cnt[i] = 0;                          // self-clean for next call
        out[i] = acc + b3[0] + g_t[i];
    }
}

// ---------------- launch (PDL on the dependent chain) ----------------
static void launch_pdl(const void* fn, dim3 grid, dim3 block, size_t smem,
                       void** args) {
    cudaLaunchConfig_t cfg = {};
    cfg.gridDim = grid;
    cfg.blockDim = block;
    cfg.dynamicSmemBytes = smem;
    cfg.stream = 0;
    cudaLaunchAttribute attr[1];
    attr[0].id = cudaLaunchAttributeProgrammaticStreamSerialization;
    attr[0].val.programmaticStreamSerializationAllowed = 1;
    cfg.attrs = attr;
    cfg.numAttrs = 1;
    cudaLaunchKernelExC(&cfg, fn, args);
}

extern "C" void kernel_launch(void* const* d_in, const int* in_sizes, int n_in,
                              void* d_out, int out_size) {
    const float* x       = (const float*)d_in[0];
    const void*  ei_raw  = d_in[1];
    const float* ew      = (const float*)d_in[2];
    const float* W1_rel  = (const float*)d_in[3];
    const float* b1      = (const float*)d_in[4];
    const float* W1_root = (const float*)d_in[5];
    const float* W2_rel  = (const float*)d_in[6];
    const float* b2      = (const float*)d_in[7];
    const float* W2_root = (const float*)d_in[8];
    const float* W3_rel  = (const float*)d_in[9];
    const float* b3      = (const float*)d_in[10];
    const float* W3_root = (const float*)d_in[11];
    float* out = (float*)d_out;

    cudaFuncSetAttribute(k_dense, cudaFuncAttributeMaxDynamicSharedMemorySize,
                         DENSE_SMEM);

    k_scatter<<<(N_EDGES / 8 + 255) / 256, 256>>>(ei_raw, ew, x);

    {
        void* args[] = {(void*)&x, (void*)&W1_rel, (void*)&b1, (void*)&W1_root,
                        (void*)&W2_rel, (void*)&b2, (void*)&W2_root};
        launch_pdl((const void*)k_dense, dim3((N_NODES + DN - 1) / DN), dim3(256),
                   DENSE_SMEM, args);
    }
    {
        void* args[] = {(void*)&W3_rel, (void*)&W3_root};
        launch_pdl((const void*)k_agg2, dim3((N_NODES * 32 + 255) / 256), dim3(256),
                   0, args);
    }
    {
        void* args[] = {(void*)&b3, (void*)&out};
        launch_pdl((const void*)k_out, dim3(((N_NODES + 3) / 4 * 32 + 255) / 256),
                   dim3(256), 0, args);
    }
}